// round 13
// baseline (speedup 1.0000x reference)
#include <cuda_runtime.h>
#include <math.h>

#define N_ANCH   172032
#define MAX_OUT  200
#define NMS_TH   0.4f
#define THRF     2.5f          // fixed compaction threshold; exactness-safe (prefix argument)
#define CAP      4096
#define M        512
#define PAIRS_BLKS 32

// ---------------- static device scratch ----------------
__device__ unsigned g_ncand;             // BSS-zero; reset by greedy phase each run
__device__ unsigned g_nc;                // working-set size (written by rank blk0)
__device__ unsigned g_done;              // last-block counter (self-resetting)
__device__ unsigned long long g_ckey[CAP];
__device__ float4   g_sb4[M];            // decoded sorted boxes (stale slots harmless)
__device__ float    g_sar[M];
__device__ int      g_sidx[M];
__device__ unsigned g_supp[M * 16];      // 512x512 suppression bits (symmetric)
__device__ float    g_scores[N_ANCH];    // exact backstop only

// ---------------- decode helper (matches reference _decode) ----------------
__device__ __forceinline__ void decode_box(const float4& rg, const float4& an,
                                           float& y1, float& x1, float& y2, float& x2,
                                           float& ar) {
    float dx = rg.x * 0.1f, dy = rg.y * 0.1f, dw = rg.z * 0.2f, dh = rg.w * 0.2f;
    float xc = dx * an.z + an.x;
    float yc = dy * an.w + an.y;
    float w  = expf(dw) * an.z;
    float h  = expf(dh) * an.w;
    y1 = yc - 0.5f * h;  x1 = xc - 0.5f * w;
    y2 = yc + 0.5f * h;  x2 = xc + 0.5f * w;
    ar = (y2 - y1) * (x2 - x1);
}

__device__ __forceinline__ float iou_f(float ay1, float ax1, float ay2, float ax2, float aar,
                                       float by1, float bx1, float by2, float bx2, float bar) {
    float ih = fmaxf(fminf(ay2, by2) - fmaxf(ay1, by1), 0.f);
    float iw = fmaxf(fminf(ax2, bx2) - fmaxf(ax1, bx1), 0.f);
    float inter = ih * iw;
    return inter / (aar + bar - inter + 1e-12f);
}

__device__ __forceinline__ void gather_one(int t, int idx, float m,
                                           const float4* __restrict__ reg4,
                                           const float*  __restrict__ lnd,
                                           const float4* __restrict__ anch4,
                                           float* __restrict__ out) {
    float4 rg = __ldg(reg4 + idx);
    float4 an = __ldg(anch4 + idx);
    float y1, x1, y2, x2, ar;
    decode_box(rg, an, y1, x1, y2, x2, ar);
    out[4 * t + 0] = y1 * m;
    out[4 * t + 1] = x1 * m;
    out[4 * t + 2] = y2 * m;
    out[4 * t + 3] = x2 * m;
    const float* lp = lnd + 10 * idx;
    float* op = out + 4 * MAX_OUT + 10 * t;
#pragma unroll
    for (int k = 0; k < 5; k++) {
        float lx = lp[2 * k]     * 0.1f * an.z + an.x;
        float ly = lp[2 * k + 1] * 0.1f * an.w + an.y;
        op[2 * k]     = lx * m;
        op[2 * k + 1] = ly * m;
    }
}

// ---------------- 1) compact candidates above fixed threshold ----------------
__global__ void compact_kernel(const float4* __restrict__ cls4, int n) {
    int nv = n >> 1;
    int v = blockIdx.x * blockDim.x + threadIdx.x;
    if (v < nv) {
        float4 c = __ldg(cls4 + v);
        if (c.y > THRF) {
            unsigned u = __float_as_uint(c.y) ^ 0x80000000u;
            unsigned pos = atomicAdd(&g_ncand, 1u);
            if (pos < CAP)
                g_ckey[pos] = ((unsigned long long)u << 32) | (unsigned)(~(unsigned)(2 * v));
        }
        if (c.w > THRF) {
            unsigned u = __float_as_uint(c.w) ^ 0x80000000u;
            unsigned pos = atomicAdd(&g_ncand, 1u);
            if (pos < CAP)
                g_ckey[pos] = ((unsigned long long)u << 32) | (unsigned)(~(unsigned)(2 * v + 1));
        }
    }
    if ((n & 1) && v == 0) {
        float s = ((const float*)cls4)[2 * (n - 1) + 1];
        if (s > THRF) {
            unsigned u = __float_as_uint(s) ^ 0x80000000u;
            unsigned pos = atomicAdd(&g_ncand, 1u);
            if (pos < CAP)
                g_ckey[pos] = ((unsigned long long)u << 32) | (unsigned)(~(unsigned)(n - 1));
        }
    }
}

// ---------------- 2) rank-scatter sort + decode top-M (multi-SM) ----------------
__global__ __launch_bounds__(256) void rank_kernel(const float4* __restrict__ reg4,
                                                   const float4* __restrict__ anch4) {
    __shared__ unsigned long long sk[CAP];
    const int t = threadIdx.x;
    unsigned nc_all = g_ncand;
    if (blockIdx.x == 0 && t == 0)
        g_nc = (nc_all > CAP) ? 0u : ((nc_all < M) ? nc_all : M);   // overflow -> exact path
    if (nc_all == 0u || nc_all > CAP) return;
    if ((unsigned)(blockIdx.x * 64) >= nc_all) return;

    unsigned ncr = (nc_all + 3u) & ~3u;
    for (int k = t; k < (int)ncr; k += 256)
        sk[k] = (k < (int)nc_all) ? g_ckey[k] : 0ULL;
    __syncthreads();

    int c = blockIdx.x * 64 + (t >> 2), h = t & 3;
    bool live = (c < (int)nc_all);
    unsigned long long mykey = live ? sk[c] : 0ULL;
    int r = 0;
    int j = h;
    for (; j + 12 < (int)ncr; j += 16) {
        r += (sk[j]      > mykey) ? 1 : 0;
        r += (sk[j + 4]  > mykey) ? 1 : 0;
        r += (sk[j + 8]  > mykey) ? 1 : 0;
        r += (sk[j + 12] > mykey) ? 1 : 0;
    }
    for (; j < (int)ncr; j += 4)
        r += (sk[j] > mykey) ? 1 : 0;
    r += __shfl_xor_sync(0xFFFFFFFFu, r, 1);
    r += __shfl_xor_sync(0xFFFFFFFFu, r, 2);
    if (live && h == 0 && r < M) {
        int idx = (int)(~(unsigned)(mykey & 0xFFFFFFFFull));
        g_sidx[r] = idx;
        float4 rg = __ldg(reg4 + idx);
        float4 an = __ldg(anch4 + idx);
        float y1, x1, y2, x2, ar;
        decode_box(rg, an, y1, x1, y2, x2, ar);
        g_sb4[r] = make_float4(y1, x1, y2, x2);
        g_sar[r] = ar;
    }
}

// ---------------- 3) fused pairs + greedy (last-block-done) ----------------
__device__ __forceinline__ unsigned lowmask(int w, int wi, int bi) {
    return (w < wi) ? 0xFFFFFFFFu : ((w == wi) ? ((1u << bi) - 1u) : 0u);
}

__global__ __launch_bounds__(256) void pairs_greedy_kernel(const float2* __restrict__ cls,
                                                           const float4* __restrict__ reg4,
                                                           const float*  __restrict__ lnd,
                                                           const float4* __restrict__ anch4,
                                                           int n, float* __restrict__ out) {
    // phase-unioned shared buffer: pairs uses sb4/sa (10KB); greedy uses ssup (32KB)+ssidx
    __shared__ unsigned char sraw[M * 16 * 4];   // 32KB
    __shared__ int      ssidx[M];                // 2KB
    __shared__ short    ssel[MAX_OUT];
    __shared__ unsigned s_sel[16], s_new[16], s_pref[16];
    __shared__ int      s_nsel;
    __shared__ unsigned s_nc;
    __shared__ int      s_last;
    const int t = threadIdx.x;

    // ---- pairs phase (all 32 blocks) ----
    {
        float4* sb = (float4*)sraw;              // 8KB
        float*  sa = (float*)(sraw + 8192);      // 2KB
        for (int k = t; k < M; k += 256) { sb[k] = g_sb4[k]; sa[k] = g_sar[k]; }
        __syncthreads();
        int gid = blockIdx.x * 256 + t;          // M*16 = 8192 words over 32 blocks
        int i = gid >> 4, w = gid & 15;
        float4 bi = sb[i];
        float  ai = sa[i];
        unsigned word = 0;
#pragma unroll 8
        for (int jj = 0; jj < 32; jj++) {
            int j = (w << 5) + jj;
            float4 bj = sb[j];
            if (iou_f(bi.x, bi.y, bi.z, bi.w, ai, bj.x, bj.y, bj.z, bj.w, sa[j]) > NMS_TH)
                word |= (1u << jj);
        }
        g_supp[gid] = word;
    }
    __threadfence();                             // publish matrix slice before arriving
    __syncthreads();                             // all threads' STG issued before t0 arrives
    if (t == 0) {
        unsigned d = atomicAdd(&g_done, 1u);
        int last = (d == PAIRS_BLKS - 1);
        if (last) g_done = 0;                    // self-reset for next replay
        s_last = last;
    }
    __syncthreads();
    if (!s_last) return;                         // only the last-done block continues

    // ---- greedy phase (single surviving block) ----
    if (t == 0) { s_nc = g_nc; g_ncand = 0; }
    unsigned* ssup = (unsigned*)sraw;            // reuse buffer: 32KB matrix
    {
        const uint4* gsup4 = (const uint4*)g_supp;
        uint4* ssup4 = (uint4*)sraw;
        for (int k = t; k < M * 4; k += 256) ssup4[k] = gsup4[k];
        for (int k = t; k < M; k += 256) ssidx[k] = g_sidx[k];
    }
    __syncthreads();
    unsigned nc = s_nc;
    if (t < 16) {
        int rem = (int)nc - t * 32;
        s_sel[t] = (rem >= 32) ? 0xFFFFFFFFu : ((rem <= 0) ? 0u : ((1u << rem) - 1u));
    }
    __syncthreads();

    // Jacobi fixed-point: sel[i] = valid[i] & !(OR_{j<i} supp[i][j] & sel[j])
    int converged = 0;
    for (int iter = 0; iter < 24; iter++) {
#pragma unroll
        for (int p = 0; p < 2; p++) {
            int i = t + (p << 8);
            int wi = i >> 5, bi = i & 31;
            const uint4* r4 = (const uint4*)&ssup[i << 4];
            unsigned acc = 0;
#pragma unroll
            for (int q = 0; q < 4; q++) {
                uint4 rv = r4[q];
                int w0 = q << 2;
                acc |= rv.x & s_sel[w0]     & lowmask(w0,     wi, bi);
                acc |= rv.y & s_sel[w0 + 1] & lowmask(w0 + 1, wi, bi);
                acc |= rv.z & s_sel[w0 + 2] & lowmask(w0 + 2, wi, bi);
                acc |= rv.w & s_sel[w0 + 3] & lowmask(w0 + 3, wi, bi);
            }
            int nb = (i < (int)nc) && (acc == 0u);
            unsigned word = __ballot_sync(0xFFFFFFFFu, nb);   // all 32 lanes execute
            if ((t & 31) == 0) s_new[i >> 5] = word;
        }
        __syncthreads();
        int mydiff = 0;
        if (t < 16) {
            mydiff = (s_new[t] != s_sel[t]);
            s_sel[t] = s_new[t];
        }
        int changed = __syncthreads_or(mydiff);
        if (!changed) { converged = 1; break; }
    }

    int nsel;
    if (converged) {
        if (t < 32) {                            // enumerate first MAX_OUT in order
            unsigned w = (t < 16) ? s_sel[t] : 0u;
            int c = __popc(w);
            int inc = c;
#pragma unroll
            for (int d = 1; d < 32; d <<= 1) {
                int v = __shfl_up_sync(0xFFFFFFFFu, inc, d);
                if (t >= (unsigned)d) inc += v;
            }
            if (t < 16) s_pref[t] = inc - c;
            if (t == 15) s_nsel = (inc > MAX_OUT) ? MAX_OUT : inc;
        }
        __syncthreads();
#pragma unroll
        for (int p = 0; p < 2; p++) {
            int i = t + (p << 8);
            unsigned w = s_sel[i >> 5];
            if ((w >> (i & 31)) & 1u) {
                int order = (int)s_pref[i >> 5] + __popc(w & ((1u << (i & 31)) - 1u));
                if (order < MAX_OUT) ssel[order] = (short)i;
            }
        }
        __syncthreads();
        nsel = s_nsel;
    } else {
        // safety net: proven warp-serial greedy (uniform branch)
        if (t < 32) {
            const unsigned FULL = 0xFFFFFFFFu;
            int lane = t;
            unsigned valid = 0;
            if (lane < 16) {
                int rem = (int)nc - lane * 32;
                valid = (rem >= 32) ? 0xFFFFFFFFu : ((rem <= 0) ? 0u : ((1u << rem) - 1u));
            }
            unsigned removed = 0;
            int ns = 0;
            while (ns < MAX_OUT) {
                unsigned alivew = valid & ~removed;
                unsigned bal = __ballot_sync(FULL, alivew != 0u);
                if (!bal) break;
                int src = __ffs(bal) - 1;
                unsigned w0 = __shfl_sync(FULL, alivew, src);
                int i = (src << 5) + __ffs(w0) - 1;
                if (lane == 0) ssel[ns] = (short)i;
                unsigned supw = (lane < 16) ? ssup[(i << 4) + lane] : 0u;
                removed |= supw;
                ns++;
            }
            if (lane == 0) s_nsel = ns;
        }
        __syncthreads();
        nsel = s_nsel;
    }

    if (nsel >= MAX_OUT) {                       // exact greedy prefix -> done
        if (t < MAX_OUT)
            gather_one(t, ssidx[ssel[t]], 1.f, reg4, lnd, anch4, out);
        return;
    }

    // ---- exact backstop (shortfall/overflow; not taken on typical data) ----
    {
        float* red_s = (float*)ssup;
        int*   red_i = (int*)(ssup + 256);
        int*   f_idx = (int*)(ssup + 512);
        int*   f_val = (int*)(ssup + 512 + MAX_OUT);
        for (int j = t; j < n; j += 256) {
            float s = cls[j].y;
            g_scores[j] = (s > NMS_TH) ? s : -INFINITY;
        }
        __syncthreads();
        for (int it = 0; it < MAX_OUT; it++) {
            float best = -INFINITY; int bi = 0;
            for (int j = t; j < n; j += 256) {
                float v = g_scores[j];
                if (v > best) { best = v; bi = j; }
            }
            red_s[t] = best; red_i[t] = bi;
            __syncthreads();
            for (int s = 128; s > 0; s >>= 1) {
                if (t < s) {
                    float vo = red_s[t + s]; int io = red_i[t + s];
                    if (vo > red_s[t] || (vo == red_s[t] && io < red_i[t])) {
                        red_s[t] = vo; red_i[t] = io;
                    }
                }
                __syncthreads();
            }
            int i = red_i[0];
            bool valid = (red_s[0] > -INFINITY);
            float4 rgi = __ldg(reg4 + i);
            float4 ani = __ldg(anch4 + i);
            float by1, bx1, by2, bx2, bar;
            decode_box(rgi, ani, by1, bx1, by2, bx2, bar);
            if (valid) {
                for (int j = t; j < n; j += 256) {
                    if (g_scores[j] > -INFINITY) {
                        float4 rg = __ldg(reg4 + j);
                        float4 an = __ldg(anch4 + j);
                        float y1, x1, y2, x2, ar;
                        decode_box(rg, an, y1, x1, y2, x2, ar);
                        if (iou_f(y1, x1, y2, x2, ar, by1, bx1, by2, bx2, bar) > NMS_TH)
                            g_scores[j] = -INFINITY;
                    }
                }
            }
            if (t == 0) { f_idx[it] = i; f_val[it] = valid ? 1 : 0; }
            __syncthreads();
        }
        if (t < MAX_OUT)
            gather_one(t, f_val[t] ? f_idx[t] : 0, f_val[t] ? 1.f : 0.f, reg4, lnd, anch4, out);
    }
}

// ---------------- launch: THREE plain kernels ----------------
extern "C" void kernel_launch(void* const* d_in, const int* in_sizes, int n_in,
                              void* d_out, int out_size) {
    const float4* cls4  = (const float4*)d_in[0];
    const float4* reg4  = (const float4*)d_in[1];
    const float*  lnd   = (const float*)d_in[2];
    const float4* anch4 = (const float4*)d_in[3];

    int n = in_sizes[0] / 2;
    if (n > N_ANCH) n = N_ANCH;
    int nv = n >> 1;

    compact_kernel<<<(nv + 255) / 256, 256>>>(cls4, n);
    rank_kernel<<<CAP / 64, 256>>>(reg4, anch4);
    pairs_greedy_kernel<<<PAIRS_BLKS, 256>>>((const float2*)cls4, reg4, lnd, anch4, n, (float*)d_out);
}

// round 14
// speedup vs baseline: 1.1936x; 1.1936x over previous
#include <cuda_runtime.h>
#include <math.h>

#define N_ANCH   172032
#define MAX_OUT  200
#define NMS_TH   0.4f
#define THRF     2.5f          // fixed compaction threshold; exactness-safe (prefix argument)
#define CAP      4096
#define M        256           // NMS working set (top-M); shortfall -> exact backstop
#define MW       (M / 32)      // mask words = 8

// ---------------- static device scratch ----------------
__device__ unsigned g_ncand;             // BSS-zero; reset by greedy each run
__device__ unsigned g_nc;                // working-set size (written by rank blk0)
__device__ unsigned long long g_ckey[CAP];
__device__ float4   g_sb4[M];            // decoded sorted boxes (stale slots harmless)
__device__ float    g_sar[M];
__device__ int      g_sidx[M];
__device__ unsigned g_supp[M * MW];      // 256x256 suppression bits (symmetric)
__device__ float    g_scores[N_ANCH];    // exact backstop only

// ---------------- decode helper (matches reference _decode) ----------------
__device__ __forceinline__ void decode_box(const float4& rg, const float4& an,
                                           float& y1, float& x1, float& y2, float& x2,
                                           float& ar) {
    float dx = rg.x * 0.1f, dy = rg.y * 0.1f, dw = rg.z * 0.2f, dh = rg.w * 0.2f;
    float xc = dx * an.z + an.x;
    float yc = dy * an.w + an.y;
    float w  = expf(dw) * an.z;
    float h  = expf(dh) * an.w;
    y1 = yc - 0.5f * h;  x1 = xc - 0.5f * w;
    y2 = yc + 0.5f * h;  x2 = xc + 0.5f * w;
    ar = (y2 - y1) * (x2 - x1);
}

__device__ __forceinline__ float iou_f(float ay1, float ax1, float ay2, float ax2, float aar,
                                       float by1, float bx1, float by2, float bx2, float bar) {
    float ih = fmaxf(fminf(ay2, by2) - fmaxf(ay1, by1), 0.f);
    float iw = fmaxf(fminf(ax2, bx2) - fmaxf(ax1, bx1), 0.f);
    float inter = ih * iw;
    return inter / (aar + bar - inter + 1e-12f);
}

__device__ __forceinline__ void gather_one(int t, int idx, float m,
                                           const float4* __restrict__ reg4,
                                           const float*  __restrict__ lnd,
                                           const float4* __restrict__ anch4,
                                           float* __restrict__ out) {
    float4 rg = __ldg(reg4 + idx);
    float4 an = __ldg(anch4 + idx);
    float y1, x1, y2, x2, ar;
    decode_box(rg, an, y1, x1, y2, x2, ar);
    out[4 * t + 0] = y1 * m;
    out[4 * t + 1] = x1 * m;
    out[4 * t + 2] = y2 * m;
    out[4 * t + 3] = x2 * m;
    const float* lp = lnd + 10 * idx;
    float* op = out + 4 * MAX_OUT + 10 * t;
#pragma unroll
    for (int k = 0; k < 5; k++) {
        float lx = lp[2 * k]     * 0.1f * an.z + an.x;
        float ly = lp[2 * k + 1] * 0.1f * an.w + an.y;
        op[2 * k]     = lx * m;
        op[2 * k + 1] = ly * m;
    }
}

// ---------------- 1) compact candidates above fixed threshold ----------------
__global__ void compact_kernel(const float4* __restrict__ cls4, int n) {
    int nv = n >> 1;                          // one float4 = two (cls0,score) pairs
    int base = blockIdx.x * blockDim.x + threadIdx.x;
    int stride = gridDim.x * blockDim.x;
    for (int v = base; v < nv; v += stride) {
        float4 c = __ldg(cls4 + v);
        if (c.y > THRF) {
            unsigned u = __float_as_uint(c.y) ^ 0x80000000u;
            unsigned pos = atomicAdd(&g_ncand, 1u);
            if (pos < CAP)
                g_ckey[pos] = ((unsigned long long)u << 32) | (unsigned)(~(unsigned)(2 * v));
        }
        if (c.w > THRF) {
            unsigned u = __float_as_uint(c.w) ^ 0x80000000u;
            unsigned pos = atomicAdd(&g_ncand, 1u);
            if (pos < CAP)
                g_ckey[pos] = ((unsigned long long)u << 32) | (unsigned)(~(unsigned)(2 * v + 1));
        }
    }
    if ((n & 1) && base == 0) {               // generality guard (n is even here)
        float s = ((const float*)cls4)[2 * (n - 1) + 1];
        if (s > THRF) {
            unsigned u = __float_as_uint(s) ^ 0x80000000u;
            unsigned pos = atomicAdd(&g_ncand, 1u);
            if (pos < CAP)
                g_ckey[pos] = ((unsigned long long)u << 32) | (unsigned)(~(unsigned)(n - 1));
        }
    }
}

// ---------------- 2) rank-scatter sort + decode top-M (multi-SM) ----------------
__global__ __launch_bounds__(256) void rank_kernel(const float4* __restrict__ reg4,
                                                   const float4* __restrict__ anch4) {
    __shared__ unsigned long long sk[CAP];
    const int t = threadIdx.x;
    unsigned nc_all = g_ncand;
    if (blockIdx.x == 0 && t == 0)
        g_nc = (nc_all > CAP) ? 0u : ((nc_all < M) ? nc_all : M);   // overflow -> exact path
    if (nc_all == 0u || nc_all > CAP) return;
    if ((unsigned)(blockIdx.x * 64) >= nc_all) return;

    unsigned ncr = (nc_all + 3u) & ~3u;
    for (int k = t; k < (int)ncr; k += 256)
        sk[k] = (k < (int)nc_all) ? g_ckey[k] : 0ULL;
    __syncthreads();

    int c = blockIdx.x * 64 + (t >> 2), h = t & 3;
    bool live = (c < (int)nc_all);
    unsigned long long mykey = live ? sk[c] : 0ULL;
    int r = 0;
    int j = h;
    for (; j + 12 < (int)ncr; j += 16) {      // 4 independent LDS -> MLP
        r += (sk[j]      > mykey) ? 1 : 0;
        r += (sk[j + 4]  > mykey) ? 1 : 0;
        r += (sk[j + 8]  > mykey) ? 1 : 0;
        r += (sk[j + 12] > mykey) ? 1 : 0;
    }
    for (; j < (int)ncr; j += 4)
        r += (sk[j] > mykey) ? 1 : 0;
    r += __shfl_xor_sync(0xFFFFFFFFu, r, 1);  // warp-uniform: all lanes execute
    r += __shfl_xor_sync(0xFFFFFFFFu, r, 2);
    if (live && h == 0 && r < M) {            // ranks unique -> race-free scatter
        int idx = (int)(~(unsigned)(mykey & 0xFFFFFFFFull));
        g_sidx[r] = idx;
        float4 rg = __ldg(reg4 + idx);
        float4 an = __ldg(anch4 + idx);
        float y1, x1, y2, x2, ar;
        decode_box(rg, an, y1, x1, y2, x2, ar);
        g_sb4[r] = make_float4(y1, x1, y2, x2);
        g_sar[r] = ar;
    }
}

// ---------------- 3) pairwise suppression bitmask (multi-SM, 8 blocks) ----------------
__global__ __launch_bounds__(256) void pairs_kernel() {
    __shared__ float4 sb[M];                  // 4KB
    __shared__ float  sa[M];                  // 1KB
    const int t = threadIdx.x;
    sb[t] = g_sb4[t];
    sa[t] = g_sar[t];
    __syncthreads();
    int gid = blockIdx.x * 256 + t;           // M*MW = 2048 words over 8 blocks
    int i = gid >> 3, w = gid & 7;
    float4 bi = sb[i];
    float  ai = sa[i];
    unsigned word = 0;
#pragma unroll 8
    for (int jj = 0; jj < 32; jj++) {
        int j = (w << 5) + jj;
        float4 bj = sb[j];
        if (iou_f(bi.x, bi.y, bi.z, bi.w, ai, bj.x, bj.y, bj.z, bj.w, sa[j]) > NMS_TH)
            word |= (1u << jj);
    }
    g_supp[(i << 3) + w] = word;
}

// ---------------- 4) fixed-point greedy + gather (single block) ----------------
__device__ __forceinline__ unsigned lowmask(int w, int wi, int bi) {
    return (w < wi) ? 0xFFFFFFFFu : ((w == wi) ? ((1u << bi) - 1u) : 0u);
}

__global__ __launch_bounds__(256) void greedy_kernel(const float2* __restrict__ cls,
                                                     const float4* __restrict__ reg4,
                                                     const float*  __restrict__ lnd,
                                                     const float4* __restrict__ anch4,
                                                     int n, float* __restrict__ out) {
    __shared__ unsigned ssup[M * MW];         // 8KB suppression matrix
    __shared__ int      ssidx[M];
    __shared__ short    ssel[MAX_OUT];
    __shared__ unsigned s_sel[MW], s_new[MW], s_pref[MW];
    __shared__ int      s_nsel;
    __shared__ unsigned s_nc;
    const int t = threadIdx.x;

    if (t == 0) { s_nc = g_nc; g_ncand = 0; } // snapshot + replay reset (barrier below)
    {   // vectorized preload: M*MW/4 = 512 uint4 over 256 threads
        const uint4* gsup4 = (const uint4*)g_supp;
        uint4* ssup4 = (uint4*)ssup;
        ssup4[t]       = gsup4[t];
        ssup4[t + 256] = gsup4[t + 256];
        ssidx[t] = g_sidx[t];
    }
    __syncthreads();
    unsigned nc = s_nc;
    if (t < MW) {
        int rem = (int)nc - t * 32;
        s_sel[t] = (rem >= 32) ? 0xFFFFFFFFu : ((rem <= 0) ? 0u : ((1u << rem) - 1u));
    }
    __syncthreads();

    // ---- Jacobi fixed-point: sel[i] = valid[i] & !(OR_{j<i} supp[i][j] & sel[j]) ----
    int converged = 0;
    for (int iter = 0; iter < 24; iter++) {
        int i = t;                             // one candidate per thread
        int wi = i >> 5, bi = i & 31;
        const uint4* r4 = (const uint4*)&ssup[i << 3];
        unsigned acc = 0;
#pragma unroll
        for (int q = 0; q < MW / 4; q++) {
            uint4 rv = r4[q];
            int w0 = q << 2;
            acc |= rv.x & s_sel[w0]     & lowmask(w0,     wi, bi);
            acc |= rv.y & s_sel[w0 + 1] & lowmask(w0 + 1, wi, bi);
            acc |= rv.z & s_sel[w0 + 2] & lowmask(w0 + 2, wi, bi);
            acc |= rv.w & s_sel[w0 + 3] & lowmask(w0 + 3, wi, bi);
        }
        int nb = (i < (int)nc) && (acc == 0u);
        unsigned word = __ballot_sync(0xFFFFFFFFu, nb);   // all 32 lanes execute
        if ((t & 31) == 0) s_new[t >> 5] = word;
        __syncthreads();
        int mydiff = 0;
        if (t < MW) {
            mydiff = (s_new[t] != s_sel[t]);
            s_sel[t] = s_new[t];
        }
        int changed = __syncthreads_or(mydiff);
        if (!changed) { converged = 1; break; }
    }

    int nsel;
    if (converged) {
        if (t < 32) {                          // enumerate first MAX_OUT selected, in order
            unsigned w = (t < MW) ? s_sel[t] : 0u;
            int c = __popc(w);
            int inc = c;
#pragma unroll
            for (int d = 1; d < 32; d <<= 1) {
                int v = __shfl_up_sync(0xFFFFFFFFu, inc, d);
                if (t >= (unsigned)d) inc += v;
            }
            if (t < MW) s_pref[t] = inc - c;   // exclusive prefix
            if (t == MW - 1) s_nsel = (inc > MAX_OUT) ? MAX_OUT : inc;
        }
        __syncthreads();
        {
            int i = t;
            unsigned w = s_sel[i >> 5];
            if ((w >> (i & 31)) & 1u) {
                int order = (int)s_pref[i >> 5] + __popc(w & ((1u << (i & 31)) - 1u));
                if (order < MAX_OUT) ssel[order] = (short)i;
            }
        }
        __syncthreads();
        nsel = s_nsel;
    } else {
        // safety net: proven warp-serial greedy (uniform branch)
        if (t < 32) {
            const unsigned FULL = 0xFFFFFFFFu;
            int lane = t;
            unsigned valid = 0;
            if (lane < MW) {
                int rem = (int)nc - lane * 32;
                valid = (rem >= 32) ? 0xFFFFFFFFu : ((rem <= 0) ? 0u : ((1u << rem) - 1u));
            }
            unsigned removed = 0;
            int ns = 0;
            while (ns < MAX_OUT) {
                unsigned alivew = valid & ~removed;
                unsigned bal = __ballot_sync(FULL, alivew != 0u);
                if (!bal) break;
                int src = __ffs(bal) - 1;
                unsigned w0 = __shfl_sync(FULL, alivew, src);
                int i = (src << 5) + __ffs(w0) - 1;
                if (lane == 0) ssel[ns] = (short)i;
                unsigned supw = (lane < MW) ? ssup[(i << 3) + lane] : 0u;
                removed |= supw;
                ns++;
            }
            if (lane == 0) s_nsel = ns;
        }
        __syncthreads();
        nsel = s_nsel;
    }

    if (nsel >= MAX_OUT) {                     // exact greedy prefix -> done
        if (t < MAX_OUT)
            gather_one(t, ssidx[ssel[t]], 1.f, reg4, lnd, anch4, out);
        return;
    }

    // ---- exact backstop (shortfall/overflow; not taken on typical data) ----
    {
        float* red_s = (float*)ssup;
        int*   red_i = (int*)(ssup + 256);
        int*   f_idx = (int*)(ssup + 512);
        int*   f_val = (int*)(ssup + 512 + MAX_OUT);
        for (int j = t; j < n; j += 256) {
            float s = cls[j].y;
            g_scores[j] = (s > NMS_TH) ? s : -INFINITY;
        }
        __syncthreads();
        for (int it = 0; it < MAX_OUT; it++) {
            float best = -INFINITY; int bi = 0;
            for (int j = t; j < n; j += 256) {
                float v = g_scores[j];
                if (v > best) { best = v; bi = j; }
            }
            red_s[t] = best; red_i[t] = bi;
            __syncthreads();
            for (int s = 128; s > 0; s >>= 1) {
                if (t < s) {
                    float vo = red_s[t + s]; int io = red_i[t + s];
                    if (vo > red_s[t] || (vo == red_s[t] && io < red_i[t])) {
                        red_s[t] = vo; red_i[t] = io;
                    }
                }
                __syncthreads();
            }
            int i = red_i[0];
            bool valid = (red_s[0] > -INFINITY);
            float4 rgi = __ldg(reg4 + i);
            float4 ani = __ldg(anch4 + i);
            float by1, bx1, by2, bx2, bar;
            decode_box(rgi, ani, by1, bx1, by2, bx2, bar);
            if (valid) {
                for (int j = t; j < n; j += 256) {
                    if (g_scores[j] > -INFINITY) {
                        float4 rg = __ldg(reg4 + j);
                        float4 an = __ldg(anch4 + j);
                        float y1, x1, y2, x2, ar;
                        decode_box(rg, an, y1, x1, y2, x2, ar);
                        if (iou_f(y1, x1, y2, x2, ar, by1, bx1, by2, bx2, bar) > NMS_TH)
                            g_scores[j] = -INFINITY;
                    }
                }
            }
            if (t == 0) { f_idx[it] = i; f_val[it] = valid ? 1 : 0; }
            __syncthreads();
        }
        if (t < MAX_OUT)
            gather_one(t, f_val[t] ? f_idx[t] : 0, f_val[t] ? 1.f : 0.f, reg4, lnd, anch4, out);
    }
}

// ---------------- launch: FOUR plain kernels ----------------
extern "C" void kernel_launch(void* const* d_in, const int* in_sizes, int n_in,
                              void* d_out, int out_size) {
    const float4* cls4  = (const float4*)d_in[0];
    const float4* reg4  = (const float4*)d_in[1];
    const float*  lnd   = (const float*)d_in[2];
    const float4* anch4 = (const float4*)d_in[3];

    int n = in_sizes[0] / 2;
    if (n > N_ANCH) n = N_ANCH;

    compact_kernel<<<168, 256>>>(cls4, n);
    rank_kernel<<<CAP / 64, 256>>>(reg4, anch4);
    pairs_kernel<<<M * MW / 256, 256>>>();
    greedy_kernel<<<1, 256>>>((const float2*)cls4, reg4, lnd, anch4, n, (float*)d_out);
}

// round 15
// speedup vs baseline: 1.3464x; 1.1280x over previous
#include <cuda_runtime.h>
#include <math.h>

#define N_ANCH   172032
#define MAX_OUT  200
#define NMS_TH   0.4f
#define THRF     2.9f          // fixed compaction threshold; exactness-safe (prefix argument)
#define CAP      4096
#define M        256           // NMS working set (top-M); shortfall -> exact backstop
#define MW       (M / 32)      // mask words = 8

// ---------------- static device scratch ----------------
__device__ unsigned g_ncand;             // BSS-zero; reset by greedy each run
__device__ unsigned g_nc;                // working-set size (written by rank blk0)
__device__ unsigned long long g_ckey[CAP];
__device__ float4   g_sb4[M];            // decoded sorted boxes (stale slots harmless)
__device__ float4   g_san[M];            // anchors of sorted candidates (for gather)
__device__ float    g_sar[M];
__device__ int      g_sidx[M];
__device__ unsigned g_supp[M * MW];      // 256x256 suppression bits (symmetric)
__device__ float    g_scores[N_ANCH];    // exact backstop only

// ---------------- decode helper (matches reference _decode) ----------------
__device__ __forceinline__ void decode_box(const float4& rg, const float4& an,
                                           float& y1, float& x1, float& y2, float& x2,
                                           float& ar) {
    float dx = rg.x * 0.1f, dy = rg.y * 0.1f, dw = rg.z * 0.2f, dh = rg.w * 0.2f;
    float xc = dx * an.z + an.x;
    float yc = dy * an.w + an.y;
    float w  = expf(dw) * an.z;
    float h  = expf(dh) * an.w;
    y1 = yc - 0.5f * h;  x1 = xc - 0.5f * w;
    y2 = yc + 0.5f * h;  x2 = xc + 0.5f * w;
    ar = (y2 - y1) * (x2 - x1);
}

__device__ __forceinline__ float iou_f(float ay1, float ax1, float ay2, float ax2, float aar,
                                       float by1, float bx1, float by2, float bx2, float bar) {
    float ih = fmaxf(fminf(ay2, by2) - fmaxf(ay1, by1), 0.f);
    float iw = fmaxf(fminf(ax2, bx2) - fmaxf(ax1, bx1), 0.f);
    float inter = ih * iw;
    return inter / (aar + bar - inter + 1e-12f);
}

// full re-decode gather (exact backstop path only)
__device__ __forceinline__ void gather_one(int t, int idx, float m,
                                           const float4* __restrict__ reg4,
                                           const float*  __restrict__ lnd,
                                           const float4* __restrict__ anch4,
                                           float* __restrict__ out) {
    float4 rg = __ldg(reg4 + idx);
    float4 an = __ldg(anch4 + idx);
    float y1, x1, y2, x2, ar;
    decode_box(rg, an, y1, x1, y2, x2, ar);
    out[4 * t + 0] = y1 * m;
    out[4 * t + 1] = x1 * m;
    out[4 * t + 2] = y2 * m;
    out[4 * t + 3] = x2 * m;
    const float* lp = lnd + 10 * idx;
    float* op = out + 4 * MAX_OUT + 10 * t;
#pragma unroll
    for (int k = 0; k < 5; k++) {
        float lx = lp[2 * k]     * 0.1f * an.z + an.x;
        float ly = lp[2 * k + 1] * 0.1f * an.w + an.y;
        op[2 * k]     = lx * m;
        op[2 * k + 1] = ly * m;
    }
}

// ---------------- 1) compact candidates above fixed threshold ----------------
__global__ void compact_kernel(const float4* __restrict__ cls4, int n) {
    int nv = n >> 1;                          // one float4 = two (cls0,score) pairs
    int base = blockIdx.x * blockDim.x + threadIdx.x;
    int stride = gridDim.x * blockDim.x;
    for (int v = base; v < nv; v += stride) {
        float4 c = __ldg(cls4 + v);
        if (c.y > THRF) {
            unsigned u = __float_as_uint(c.y) ^ 0x80000000u;
            unsigned pos = atomicAdd(&g_ncand, 1u);
            if (pos < CAP)
                g_ckey[pos] = ((unsigned long long)u << 32) | (unsigned)(~(unsigned)(2 * v));
        }
        if (c.w > THRF) {
            unsigned u = __float_as_uint(c.w) ^ 0x80000000u;
            unsigned pos = atomicAdd(&g_ncand, 1u);
            if (pos < CAP)
                g_ckey[pos] = ((unsigned long long)u << 32) | (unsigned)(~(unsigned)(2 * v + 1));
        }
    }
    if ((n & 1) && base == 0) {               // generality guard (n is even here)
        float s = ((const float*)cls4)[2 * (n - 1) + 1];
        if (s > THRF) {
            unsigned u = __float_as_uint(s) ^ 0x80000000u;
            unsigned pos = atomicAdd(&g_ncand, 1u);
            if (pos < CAP)
                g_ckey[pos] = ((unsigned long long)u << 32) | (unsigned)(~(unsigned)(n - 1));
        }
    }
}

// ---------------- 2) rank-scatter sort + decode top-M (multi-SM) ----------------
__global__ __launch_bounds__(256) void rank_kernel(const float4* __restrict__ reg4,
                                                   const float4* __restrict__ anch4) {
    __shared__ unsigned long long sk[CAP];
    const int t = threadIdx.x;
    unsigned nc_all = g_ncand;
    if (blockIdx.x == 0 && t == 0)
        g_nc = (nc_all > CAP) ? 0u : ((nc_all < M) ? nc_all : M);   // overflow -> exact path
    if (nc_all == 0u || nc_all > CAP) return;
    if ((unsigned)(blockIdx.x * 64) >= nc_all) return;

    unsigned ncr = (nc_all + 3u) & ~3u;
    for (int k = t; k < (int)ncr; k += 256)
        sk[k] = (k < (int)nc_all) ? g_ckey[k] : 0ULL;
    __syncthreads();

    int c = blockIdx.x * 64 + (t >> 2), h = t & 3;
    bool live = (c < (int)nc_all);
    unsigned long long mykey = live ? sk[c] : 0ULL;
    int r = 0;
    int j = h;
    for (; j + 12 < (int)ncr; j += 16) {      // 4 independent LDS -> MLP
        r += (sk[j]      > mykey) ? 1 : 0;
        r += (sk[j + 4]  > mykey) ? 1 : 0;
        r += (sk[j + 8]  > mykey) ? 1 : 0;
        r += (sk[j + 12] > mykey) ? 1 : 0;
    }
    for (; j < (int)ncr; j += 4)
        r += (sk[j] > mykey) ? 1 : 0;
    r += __shfl_xor_sync(0xFFFFFFFFu, r, 1);  // warp-uniform: all lanes execute
    r += __shfl_xor_sync(0xFFFFFFFFu, r, 2);
    if (live && h == 0 && r < M) {            // ranks unique -> race-free scatter
        int idx = (int)(~(unsigned)(mykey & 0xFFFFFFFFull));
        g_sidx[r] = idx;
        float4 rg = __ldg(reg4 + idx);
        float4 an = __ldg(anch4 + idx);
        float y1, x1, y2, x2, ar;
        decode_box(rg, an, y1, x1, y2, x2, ar);
        g_sb4[r] = make_float4(y1, x1, y2, x2);
        g_san[r] = an;
        g_sar[r] = ar;
    }
}

// ---------------- 3) pairwise suppression bitmask (multi-SM, 8 blocks) ----------------
__global__ __launch_bounds__(256) void pairs_kernel() {
    __shared__ float4 sb[M];                  // 4KB
    __shared__ float  sa[M];                  // 1KB
    const int t = threadIdx.x;
    sb[t] = g_sb4[t];
    sa[t] = g_sar[t];
    __syncthreads();
    int gid = blockIdx.x * 256 + t;           // M*MW = 2048 words over 8 blocks
    int i = gid >> 3, w = gid & 7;
    float4 bi = sb[i];
    float  ai = sa[i];
    unsigned word = 0;
#pragma unroll 8
    for (int jj = 0; jj < 32; jj++) {
        int j = (w << 5) + jj;
        float4 bj = sb[j];
        if (iou_f(bi.x, bi.y, bi.z, bi.w, ai, bj.x, bj.y, bj.z, bj.w, sa[j]) > NMS_TH)
            word |= (1u << jj);
    }
    g_supp[(i << 3) + w] = word;
}

// ---------------- 4) fixed-point greedy + gather (single block) ----------------
__device__ __forceinline__ unsigned lowmask(int w, int wi, int bi) {
    return (w < wi) ? 0xFFFFFFFFu : ((w == wi) ? ((1u << bi) - 1u) : 0u);
}

__global__ __launch_bounds__(256) void greedy_kernel(const float2* __restrict__ cls,
                                                     const float4* __restrict__ reg4,
                                                     const float*  __restrict__ lnd,
                                                     const float4* __restrict__ anch4,
                                                     int n, float* __restrict__ out) {
    __shared__ unsigned ssup[M * MW];         // 8KB suppression matrix
    __shared__ int      ssidx[M];
    __shared__ short    ssel[MAX_OUT];
    __shared__ unsigned s_sel[MW], s_new[MW], s_pref[MW];
    __shared__ int      s_nsel;
    __shared__ unsigned s_nc;
    const int t = threadIdx.x;

    if (t == 0) { s_nc = g_nc; g_ncand = 0; } // snapshot + replay reset (barrier below)
    {   // vectorized preload: M*MW/4 = 512 uint4 over 256 threads
        const uint4* gsup4 = (const uint4*)g_supp;
        uint4* ssup4 = (uint4*)ssup;
        ssup4[t]       = gsup4[t];
        ssup4[t + 256] = gsup4[t + 256];
        ssidx[t] = g_sidx[t];
    }
    __syncthreads();
    unsigned nc = s_nc;
    if (t < MW) {
        int rem = (int)nc - t * 32;
        s_sel[t] = (rem >= 32) ? 0xFFFFFFFFu : ((rem <= 0) ? 0u : ((1u << rem) - 1u));
    }
    __syncthreads();

    // ---- Jacobi fixed-point: sel[i] = valid[i] & !(OR_{j<i} supp[i][j] & sel[j]) ----
    int converged = 0;
    for (int iter = 0; iter < 24; iter++) {
        int i = t;                             // one candidate per thread
        int wi = i >> 5, bi = i & 31;
        const uint4* r4 = (const uint4*)&ssup[i << 3];
        unsigned acc = 0;
#pragma unroll
        for (int q = 0; q < MW / 4; q++) {
            uint4 rv = r4[q];
            int w0 = q << 2;
            acc |= rv.x & s_sel[w0]     & lowmask(w0,     wi, bi);
            acc |= rv.y & s_sel[w0 + 1] & lowmask(w0 + 1, wi, bi);
            acc |= rv.z & s_sel[w0 + 2] & lowmask(w0 + 2, wi, bi);
            acc |= rv.w & s_sel[w0 + 3] & lowmask(w0 + 3, wi, bi);
        }
        int nb = (i < (int)nc) && (acc == 0u);
        unsigned word = __ballot_sync(0xFFFFFFFFu, nb);   // all 32 lanes execute
        if ((t & 31) == 0) s_new[t >> 5] = word;
        __syncthreads();
        int mydiff = 0;
        if (t < MW) {
            mydiff = (s_new[t] != s_sel[t]);
            s_sel[t] = s_new[t];
        }
        int changed = __syncthreads_or(mydiff);
        if (!changed) { converged = 1; break; }
    }

    int nsel;
    if (converged) {
        if (t < 32) {                          // enumerate first MAX_OUT selected, in order
            unsigned w = (t < MW) ? s_sel[t] : 0u;
            int c = __popc(w);
            int inc = c;
#pragma unroll
            for (int d = 1; d < 32; d <<= 1) {
                int v = __shfl_up_sync(0xFFFFFFFFu, inc, d);
                if (t >= (unsigned)d) inc += v;
            }
            if (t < MW) s_pref[t] = inc - c;   // exclusive prefix
            if (t == MW - 1) s_nsel = (inc > MAX_OUT) ? MAX_OUT : inc;
        }
        __syncthreads();
        {
            int i = t;
            unsigned w = s_sel[i >> 5];
            if ((w >> (i & 31)) & 1u) {
                int order = (int)s_pref[i >> 5] + __popc(w & ((1u << (i & 31)) - 1u));
                if (order < MAX_OUT) ssel[order] = (short)i;
            }
        }
        __syncthreads();
        nsel = s_nsel;
    } else {
        // safety net: proven warp-serial greedy (uniform branch)
        if (t < 32) {
            const unsigned FULL = 0xFFFFFFFFu;
            int lane = t;
            unsigned valid = 0;
            if (lane < MW) {
                int rem = (int)nc - lane * 32;
                valid = (rem >= 32) ? 0xFFFFFFFFu : ((rem <= 0) ? 0u : ((1u << rem) - 1u));
            }
            unsigned removed = 0;
            int ns = 0;
            while (ns < MAX_OUT) {
                unsigned alivew = valid & ~removed;
                unsigned bal = __ballot_sync(FULL, alivew != 0u);
                if (!bal) break;
                int src = __ffs(bal) - 1;
                unsigned w0 = __shfl_sync(FULL, alivew, src);
                int i = (src << 5) + __ffs(w0) - 1;
                if (lane == 0) ssel[ns] = (short)i;
                unsigned supw = (lane < MW) ? ssup[(i << 3) + lane] : 0u;
                removed |= supw;
                ns++;
            }
            if (lane == 0) s_nsel = ns;
        }
        __syncthreads();
        nsel = s_nsel;
    }

    if (nsel >= MAX_OUT) {                     // exact greedy prefix -> done
        if (t < MAX_OUT) {
            int r = ssel[t];                   // rank of t-th selection
            int idx = ssidx[r];                // original anchor index (for landmarks)
            float4 b  = g_sb4[r];              // decoded box (L2-hot, bit-identical)
            float4 an = g_san[r];              // anchor (L2-hot)
            out[4 * t + 0] = b.x;
            out[4 * t + 1] = b.y;
            out[4 * t + 2] = b.z;
            out[4 * t + 3] = b.w;
            const float* lp = lnd + 10 * idx;
            float* op = out + 4 * MAX_OUT + 10 * t;
#pragma unroll
            for (int k = 0; k < 5; k++) {
                float lx = lp[2 * k]     * 0.1f * an.z + an.x;
                float ly = lp[2 * k + 1] * 0.1f * an.w + an.y;
                op[2 * k]     = lx;
                op[2 * k + 1] = ly;
            }
        }
        return;
    }

    // ---- exact backstop (shortfall/overflow; not taken on typical data) ----
    {
        float* red_s = (float*)ssup;
        int*   red_i = (int*)(ssup + 256);
        int*   f_idx = (int*)(ssup + 512);
        int*   f_val = (int*)(ssup + 512 + MAX_OUT);
        for (int j = t; j < n; j += 256) {
            float s = cls[j].y;
            g_scores[j] = (s > NMS_TH) ? s : -INFINITY;
        }
        __syncthreads();
        for (int it = 0; it < MAX_OUT; it++) {
            float best = -INFINITY; int bi = 0;
            for (int j = t; j < n; j += 256) {
                float v = g_scores[j];
                if (v > best) { best = v; bi = j; }
            }
            red_s[t] = best; red_i[t] = bi;
            __syncthreads();
            for (int s = 128; s > 0; s >>= 1) {
                if (t < s) {
                    float vo = red_s[t + s]; int io = red_i[t + s];
                    if (vo > red_s[t] || (vo == red_s[t] && io < red_i[t])) {
                        red_s[t] = vo; red_i[t] = io;
                    }
                }
                __syncthreads();
            }
            int i = red_i[0];
            bool valid = (red_s[0] > -INFINITY);
            float4 rgi = __ldg(reg4 + i);
            float4 ani = __ldg(anch4 + i);
            float by1, bx1, by2, bx2, bar;
            decode_box(rgi, ani, by1, bx1, by2, bx2, bar);
            if (valid) {
                for (int j = t; j < n; j += 256) {
                    if (g_scores[j] > -INFINITY) {
                        float4 rg = __ldg(reg4 + j);
                        float4 an = __ldg(anch4 + j);
                        float y1, x1, y2, x2, ar;
                        decode_box(rg, an, y1, x1, y2, x2, ar);
                        if (iou_f(y1, x1, y2, x2, ar, by1, bx1, by2, bx2, bar) > NMS_TH)
                            g_scores[j] = -INFINITY;
                    }
                }
            }
            if (t == 0) { f_idx[it] = i; f_val[it] = valid ? 1 : 0; }
            __syncthreads();
        }
        if (t < MAX_OUT)
            gather_one(t, f_val[t] ? f_idx[t] : 0, f_val[t] ? 1.f : 0.f, reg4, lnd, anch4, out);
    }
}

// ---------------- launch: FOUR plain kernels ----------------
extern "C" void kernel_launch(void* const* d_in, const int* in_sizes, int n_in,
                              void* d_out, int out_size) {
    const float4* cls4  = (const float4*)d_in[0];
    const float4* reg4  = (const float4*)d_in[1];
    const float*  lnd   = (const float*)d_in[2];
    const float4* anch4 = (const float4*)d_in[3];

    int n = in_sizes[0] / 2;
    if (n > N_ANCH) n = N_ANCH;

    compact_kernel<<<168, 256>>>(cls4, n);
    rank_kernel<<<CAP / 64, 256>>>(reg4, anch4);
    pairs_kernel<<<M * MW / 256, 256>>>();
    greedy_kernel<<<1, 256>>>((const float2*)cls4, reg4, lnd, anch4, n, (float*)d_out);
}